// round 14
// baseline (speedup 1.0000x reference)
#include <cuda_runtime.h>
#include <cuda_fp16.h>

#define D_ 160
#define H_ 192
#define W_ 160
#define HW_ (H_ * W_)
#define N_ (D_ * H_ * W_)          // 4,915,200
#define NP_ (N_ / 2)                // voxel pairs
#define R_ 4
#define INV_WSZ (1.0f / 729.0f)

#define W2 (W_ / 2)                 // 80 float2 lanes per row
#define HSUB 32                     // output rows per 80-lane group
#define NHCH (H_ / (2 * HSUB))      // 3 (each block = 2 groups = 64 rows)
#define NBLK_WH (D_ * NHCH)         // 480
#define GBLK 768
#define TPB1 160

#define DCHUNK 10
#define HW2 (HW_ / 2)               // 15360 half2 positions per slice
#define GRID3X (HW2 / 512)          // 30
#define GRID3Y (D_ / DCHUNK)        // 16
#define NPART3 (GRID3X * GRID3Y)    // 480

// Scratch — W+H box sums in fp16, channel-paired for wide loads/stores
__device__ float2  g_P01[NP_];
__device__ float2  g_P23[NP_];
__device__ __half2 g_P4[NP_];
__device__ float g_ccpart[NPART3];
__device__ float g_gpart[GBLK * 3];
__device__ unsigned int g_cnt;

__device__ __forceinline__ float pack_h2(__half2 h)
{
    return __uint_as_float(*reinterpret_cast<unsigned int*>(&h));
}
__device__ __forceinline__ __half2 unpack_h2(float f)
{
    unsigned int u = __float_as_uint(f);
    return *reinterpret_cast<__half2*>(&u);
}

// Simplified LNCC term: cross = S4 - S0*S1/729, Iv = S2 - S0^2/729, Jv = S3 - S1^2/729
__device__ __forceinline__ float ccf(float s0, float s1, float s2, float s3, float s4)
{
    const float cross = fmaf(-s0 * s1, INV_WSZ, s4);
    const float Iv    = fmaf(-s0 * s0, INV_WSZ, s2);
    const float Jv    = fmaf(-s1 * s1, INV_WSZ, s3);
    return __fdividef(cross * cross, fmaf(Iv, Jv, 1e-5f));
}

// ---------------------------------------------------------------------------
// Kernel 1, blocks [0, NBLK_WH): fused W+H box-sum, 2 voxels/thread.
// The 9-row H-window ring lives in REGISTERS: the h-loop is fully unrolled
// (40 iterations) so ring slots (k%9) are static. Smem is only the ping-pong
// input row buffers (~5.4 KB) -> occupancy becomes register-bound.
// Blocks [NBLK_WH, +GBLK): gradient-loss partials (no div/mod in hot loop).
// ---------------------------------------------------------------------------
__global__ void __launch_bounds__(TPB1) k_A(const float* __restrict__ I,
                                            const float* __restrict__ J,
                                            const float* __restrict__ dsp)
{
    const int bid = blockIdx.x;
    const int tid = threadIdx.x;

    if (bid == 0 && tid == 0) g_cnt = 0u;   // reset for graph replay

    if (bid < NBLK_WH) {
        __shared__ float2  bI[2][2][W2 + 4];   // [group][pp][cell]
        __shared__ float2  bJ[2][2][W2 + 4];

        const int g    = tid / W2;             // 0 or 1
        const int lane = tid % W2;             // 0..79
        const int d    = bid / NHCH;
        const int hg0  = (bid % NHCH) * (2 * HSUB) + g * HSUB;

        if (lane < 2) {
#pragma unroll
            for (int pp = 0; pp < 2; pp++) {
                bI[g][pp][lane] = make_float2(0.f, 0.f);
                bI[g][pp][W2 + 2 + lane] = make_float2(0.f, 0.f);
                bJ[g][pp][lane] = make_float2(0.f, 0.f);
                bJ[g][pp][W2 + 2 + lane] = make_float2(0.f, 0.f);
            }
        }

        const float2* __restrict__ I2p = (const float2*)(I + (size_t)d * HW_);
        const float2* __restrict__ J2p = (const float2*)(J + (size_t)d * HW_);

        // register ring: 5 channels x 9 slots of half2
        __half2 rg0[9], rg1[9], rg2[9], rg3[9], rg4[9];

        float2 S0 = {0.f,0.f}, S1 = {0.f,0.f}, S2 = {0.f,0.f},
               S3 = {0.f,0.f}, S4 = {0.f,0.f};

        {   // preload first row (hg0-R) into pp buffer 0
            const int h = hg0 - R_;
            float2 a = {0.f,0.f}, b = {0.f,0.f};
            if (h >= 0) { a = I2p[h * W2 + lane]; b = J2p[h * W2 + lane]; }
            bI[g][0][lane + 2] = a;
            bJ[g][0][lane + 2] = b;
        }
        __syncthreads();

#pragma unroll
        for (int k = 0; k < HSUB + 2 * R_; k++) {      // 40 iters, fully unrolled
            const int cur = k & 1;
            const int h   = hg0 - R_ + k;

            // prefetch next row
            float2 nI = {0.f,0.f}, nJ = {0.f,0.f};
            const int hn = h + 1;
            if (hn >= 0 && hn < H_) {
                nI = I2p[hn * W2 + lane];
                nJ = J2p[hn * W2 + lane];
            }

            // gather 10 input values per array (5 aligned float2 cells)
            float vI[10], vJ[10];
#pragma unroll
            for (int j = 0; j < 5; j++) {
                const float2 cI = bI[g][cur][lane + j];
                const float2 cJ = bJ[g][cur][lane + j];
                vI[2*j] = cI.x; vI[2*j+1] = cI.y;
                vJ[2*j] = cJ.x; vJ[2*j+1] = cJ.y;
            }

            // even output = taps 0..8; odd = even - ch(0) + ch(9)
            float e0=0.f,e1=0.f,e2=0.f,e3=0.f,e4=0.f;
#pragma unroll
            for (int i = 0; i < 9; i++) {
                const float a = vI[i], b = vJ[i];
                e0 += a; e1 += b; e2 += a*a; e3 += b*b; e4 += a*b;
            }
            const float o0 = e0 - vI[0] + vI[9];
            const float o1 = e1 - vJ[0] + vJ[9];
            const float o2 = e2 - vI[0]*vI[0] + vI[9]*vI[9];
            const float o3 = e3 - vJ[0]*vJ[0] + vJ[9]*vJ[9];
            const float o4 = e4 - vI[0]*vJ[0] + vI[9]*vJ[9];

            // accumulate unrounded; store rounded in register ring (slot static)
            const int slot = k % 9;
            rg0[slot] = __floats2half2_rn(e0, o0); S0.x += e0; S0.y += o0;
            rg1[slot] = __floats2half2_rn(e1, o1); S1.x += e1; S1.y += o1;
            rg2[slot] = __floats2half2_rn(e2, o2); S2.x += e2; S2.y += o2;
            rg3[slot] = __floats2half2_rn(e3, o3); S3.x += e3; S3.y += o3;
            rg4[slot] = __floats2half2_rn(e4, o4); S4.x += e4; S4.y += o4;

            if (k >= 2 * R_) {                          // output + subtract (static)
                const int ho = h - R_;                  // in [hg0, hg0+HSUB)
                const size_t ob = (((size_t)d * HW_ + (size_t)ho * W_) >> 1) + lane;
                g_P01[ob] = make_float2(pack_h2(__floats2half2_rn(S0.x, S0.y)),
                                        pack_h2(__floats2half2_rn(S1.x, S1.y)));
                g_P23[ob] = make_float2(pack_h2(__floats2half2_rn(S2.x, S2.y)),
                                        pack_h2(__floats2half2_rn(S3.x, S3.y)));
                g_P4[ob]  = __floats2half2_rn(S4.x, S4.y);

                const int ls = (k - 2 * R_) % 9;        // static after unroll
                float2 f;
                f = __half22float2(rg0[ls]); S0.x -= f.x; S0.y -= f.y;
                f = __half22float2(rg1[ls]); S1.x -= f.x; S1.y -= f.y;
                f = __half22float2(rg2[ls]); S2.x -= f.x; S2.y -= f.y;
                f = __half22float2(rg3[ls]); S3.x -= f.x; S3.y -= f.y;
                f = __half22float2(rg4[ls]); S4.x -= f.x; S4.y -= f.y;
            }

            bI[g][cur ^ 1][lane + 2] = nI;
            bJ[g][cur ^ 1][lane + 2] = nJ;
            __syncthreads();
        }
    } else {
        // ----- gradient-loss partials; per-thread indices loop-invariant -----
        const int gid = bid - NBLK_WH;
        const int W4 = W_ / 4;                  // 40
        const int STRIDE = GBLK * TPB1;         // 122,880
        const float4* __restrict__ p4 = (const float4*)dsp;
        const float*  __restrict__ pf = dsp;
        const int w = tid;

        const int base = gid * TPB1 + w;        // < STRIDE
        const int wv  = base % W4;
        const int hh  = (base / W4) % H_;
        const int dd0 = base / (W4 * H_);       // 0..15
        const bool doW = (wv < W4 - 1);
        const bool doH = (hh < H_ - 1);

        float aH = 0.f, aD = 0.f, aW = 0.f;
        int i = base;
#pragma unroll
        for (int c = 0; c < 3; c++) {
#pragma unroll
            for (int j = 0; j < 10; j++) {
                const float4 v = p4[i];
                float t;
                t = v.y - v.x; aW += t * t;
                t = v.z - v.y; aW += t * t;
                t = v.w - v.z; aW += t * t;
                if (doW) { t = pf[i * 4 + 4] - v.w; aW += t * t; }
                if (doH) {
                    const float4 u = p4[i + W4];
                    t = u.x - v.x; aH += t * t;
                    t = u.y - v.y; aH += t * t;
                    t = u.z - v.z; aH += t * t;
                    t = u.w - v.w; aH += t * t;
                }
                if (dd0 + 16 * j < D_ - 1) {
                    const float4 u = p4[i + HW_ / 4];
                    t = u.x - v.x; aD += t * t;
                    t = u.y - v.y; aD += t * t;
                    t = u.z - v.z; aD += t * t;
                    t = u.w - v.w; aD += t * t;
                }
                i += STRIDE;
            }
        }

        __shared__ float sh[3][TPB1];
        sh[0][w] = aH; sh[1][w] = aD; sh[2][w] = aW;
        __syncthreads();
        if (w < 80) { sh[0][w] += sh[0][w+80]; sh[1][w] += sh[1][w+80]; sh[2][w] += sh[2][w+80]; }
        __syncthreads();
        if (w < 40) { sh[0][w] += sh[0][w+40]; sh[1][w] += sh[1][w+40]; sh[2][w] += sh[2][w+40]; }
        __syncthreads();
        if (w < 20) { sh[0][w] += sh[0][w+20]; sh[1][w] += sh[1][w+20]; sh[2][w] += sh[2][w+20]; }
        __syncthreads();
        if (w < 10) { sh[0][w] += sh[0][w+10]; sh[1][w] += sh[1][w+10]; sh[2][w] += sh[2][w+10]; }
        __syncthreads();
        if (w < 5)  { sh[0][w] += sh[0][w+5];  sh[1][w] += sh[1][w+5];  sh[2][w] += sh[2][w+5];  }
        __syncthreads();
        if (w == 0) {
            g_gpart[gid * 3 + 0] = sh[0][0] + sh[0][1] + sh[0][2] + sh[0][3] + sh[0][4];
            g_gpart[gid * 3 + 1] = sh[1][0] + sh[1][1] + sh[1][2] + sh[1][3] + sh[1][4];
            g_gpart[gid * 3 + 2] = sh[2][0] + sh[2][1] + sh[2][2] + sh[2][3] + sh[2][4];
        }
    }
}

// ---------------------------------------------------------------------------
// Kernel 2: D-axis running box sum over paired channels (2 voxels/thread)
// fused with simplified cc formula + block reduction; last block combines.
// grid = (30, 16), block = 512.  (R11-proven, unchanged.)
// ---------------------------------------------------------------------------
__global__ void __launch_bounds__(512) k_B(float* __restrict__ out)
{
    const int t = threadIdx.x;
    const int p  = blockIdx.x * 512 + t;     // half2 position in a slice
    const int d0 = blockIdx.y * DCHUNK;

    float2 S0 = {0.f, 0.f}, S1 = {0.f, 0.f}, S2 = {0.f, 0.f},
           S3 = {0.f, 0.f}, S4 = {0.f, 0.f};

#pragma unroll
    for (int dd = d0 - R_; dd < d0 + R_; dd++) {
        if (dd >= 0 && dd < D_) {
            const int o = dd * HW2 + p;
            const float2 a = g_P01[o];
            const float2 b = g_P23[o];
            const __half2 c = g_P4[o];
            float2 v;
            v = __half22float2(unpack_h2(a.x)); S0.x += v.x; S0.y += v.y;
            v = __half22float2(unpack_h2(a.y)); S1.x += v.x; S1.y += v.y;
            v = __half22float2(unpack_h2(b.x)); S2.x += v.x; S2.y += v.y;
            v = __half22float2(unpack_h2(b.y)); S3.x += v.x; S3.y += v.y;
            v = __half22float2(c);              S4.x += v.x; S4.y += v.y;
        }
    }

    float acc = 0.f;
    for (int d = d0; d < d0 + DCHUNK; d++) {
        const int dn = d + R_;
        if (dn < D_) {
            const int o = dn * HW2 + p;
            const float2 a = g_P01[o];
            const float2 b = g_P23[o];
            const __half2 c = g_P4[o];
            float2 v;
            v = __half22float2(unpack_h2(a.x)); S0.x += v.x; S0.y += v.y;
            v = __half22float2(unpack_h2(a.y)); S1.x += v.x; S1.y += v.y;
            v = __half22float2(unpack_h2(b.x)); S2.x += v.x; S2.y += v.y;
            v = __half22float2(unpack_h2(b.y)); S3.x += v.x; S3.y += v.y;
            v = __half22float2(c);              S4.x += v.x; S4.y += v.y;
        }
        acc += ccf(S0.x, S1.x, S2.x, S3.x, S4.x);
        acc += ccf(S0.y, S1.y, S2.y, S3.y, S4.y);

        const int dp = d - R_;
        if (dp >= 0) {
            const int o = dp * HW2 + p;
            const float2 a = g_P01[o];
            const float2 b = g_P23[o];
            const __half2 c = g_P4[o];
            float2 v;
            v = __half22float2(unpack_h2(a.x)); S0.x -= v.x; S0.y -= v.y;
            v = __half22float2(unpack_h2(a.y)); S1.x -= v.x; S1.y -= v.y;
            v = __half22float2(unpack_h2(b.x)); S2.x -= v.x; S2.y -= v.y;
            v = __half22float2(unpack_h2(b.y)); S3.x -= v.x; S3.y -= v.y;
            v = __half22float2(c);              S4.x -= v.x; S4.y -= v.y;
        }
    }

    __shared__ float sh[512];
    sh[t] = acc;
    __syncthreads();
#pragma unroll
    for (int s = 256; s > 0; s >>= 1) {
        if (t < s) sh[t] += sh[t + s];
        __syncthreads();
    }
    if (t == 0) g_ccpart[blockIdx.y * GRID3X + blockIdx.x] = sh[0];

    // ----- last-block final combine -----
    __shared__ bool is_last;
    if (t == 0) {
        __threadfence();
        is_last = (atomicAdd(&g_cnt, 1u) == NPART3 - 1);
    }
    __syncthreads();
    if (!is_last) return;

    float cc = 0.f;
    for (int i = t; i < NPART3; i += 512) cc += g_ccpart[i];

    const float invNH = 1.0f / (3.0f * D_ * (H_ - 1) * W_);
    const float invND = 1.0f / (3.0f * (D_ - 1) * H_ * W_);
    const float invNW = 1.0f / (3.0f * D_ * H_ * (W_ - 1));

    float g = 0.f;
    for (int i = t; i < GBLK; i += 512) {
        g += g_gpart[i * 3 + 0] * invNH
           + g_gpart[i * 3 + 1] * invND
           + g_gpart[i * 3 + 2] * invNW;
    }

    __shared__ float shg[512];
    sh[t] = cc;
    shg[t] = g;
    __syncthreads();
#pragma unroll
    for (int s = 256; s > 0; s >>= 1) {
        if (t < s) { sh[t] += sh[t + s]; shg[t] += shg[t + s]; }
        __syncthreads();
    }
    if (t == 0)
        out[0] = (1.0f - sh[0] / (float)N_) + 0.01f * (shg[0] / 3.0f);
}

extern "C" void kernel_launch(void* const* d_in, const int* in_sizes, int n_in,
                              void* d_out, int out_size)
{
    const float* I   = (const float*)d_in[0];
    const float* J   = (const float*)d_in[1];
    const float* dsp = (const float*)d_in[2];
    float* out = (float*)d_out;

    k_A<<<NBLK_WH + GBLK, TPB1>>>(I, J, dsp);
    k_B<<<dim3(GRID3X, GRID3Y), 512>>>(out);
}

// round 15
// speedup vs baseline: 1.1143x; 1.1143x over previous
#include <cuda_runtime.h>
#include <cuda_fp16.h>

#define D_ 160
#define H_ 192
#define W_ 160
#define HW_ (H_ * W_)
#define N_ (D_ * H_ * W_)          // 4,915,200
#define NP_ (N_ / 2)                // voxel pairs
#define R_ 4
#define INV_WSZ (1.0f / 729.0f)

#define W2 (W_ / 2)                 // 80 float2 lanes per row
#define HSUB 32                     // output rows per 80-lane group
#define NHCH (H_ / (2 * HSUB))      // 3 (each block = 2 groups = 64 rows)
#define NBLK_WH (D_ * NHCH)         // 480
#define GBLK 768
#define TPB1 160

#define DCHUNK 10
#define HW2 (HW_ / 2)               // 15360 half2 positions per slice
#define GRID3X (HW2 / 512)          // 30
#define GRID3Y (D_ / DCHUNK)        // 16
#define NPART3 (GRID3X * GRID3Y)    // 480

// Scratch — W+H box sums in fp16, channel-paired for wide loads/stores
__device__ float2  g_P01[NP_];
__device__ float2  g_P23[NP_];
__device__ __half2 g_P4[NP_];
__device__ float g_ccpart[NPART3];
__device__ float g_gpart[GBLK * 3];
__device__ unsigned int g_cnt;

__device__ __forceinline__ float pack_h2(__half2 h)
{
    return __uint_as_float(*reinterpret_cast<unsigned int*>(&h));
}
__device__ __forceinline__ __half2 unpack_h2(float f)
{
    unsigned int u = __float_as_uint(f);
    return *reinterpret_cast<__half2*>(&u);
}

// Simplified LNCC term: cross = S4 - S0*S1/729, Iv = S2 - S0^2/729, Jv = S3 - S1^2/729
__device__ __forceinline__ float ccf(float s0, float s1, float s2, float s3, float s4)
{
    const float cross = fmaf(-s0 * s1, INV_WSZ, s4);
    const float Iv    = fmaf(-s0 * s0, INV_WSZ, s2);
    const float Jv    = fmaf(-s1 * s1, INV_WSZ, s3);
    return __fdividef(cross * cross, fmaf(Iv, Jv, 1e-5f));
}

// ---------------------------------------------------------------------------
// Kernel 1, blocks [0, NBLK_WH): fused W+H box-sum, 2 voxels/thread.
// 160 threads = 2 groups x 80 lanes; 9-slot fp16 smem ring; ping-pong float2
// row buffers (1 sync/row). Blocks [NBLK_WH, +GBLK): gradient-loss partials
// (loop-invariant index decomposition, no div/mod in the hot loop).
// (R13-proven, unchanged.)
// ---------------------------------------------------------------------------
__global__ void __launch_bounds__(TPB1) k_A(const float* __restrict__ I,
                                            const float* __restrict__ J,
                                            const float* __restrict__ dsp)
{
    const int bid = blockIdx.x;
    const int tid = threadIdx.x;

    if (bid == 0 && tid == 0) g_cnt = 0u;   // reset for graph replay

    if (bid < NBLK_WH) {
        __shared__ float2  bI[2][2][W2 + 4];   // [group][pp][cell]
        __shared__ float2  bJ[2][2][W2 + 4];
        __shared__ __half2 ring[2][9][5][W2];

        const int g    = tid / W2;             // 0 or 1
        const int lane = tid % W2;             // 0..79
        const int d    = bid / NHCH;
        const int hg0  = (bid % NHCH) * (2 * HSUB) + g * HSUB;

        if (lane < 2) {
#pragma unroll
            for (int pp = 0; pp < 2; pp++) {
                bI[g][pp][lane] = make_float2(0.f, 0.f);
                bI[g][pp][W2 + 2 + lane] = make_float2(0.f, 0.f);
                bJ[g][pp][lane] = make_float2(0.f, 0.f);
                bJ[g][pp][W2 + 2 + lane] = make_float2(0.f, 0.f);
            }
        }

        const float2* __restrict__ I2p = (const float2*)(I + (size_t)d * HW_);
        const float2* __restrict__ J2p = (const float2*)(J + (size_t)d * HW_);

        float2 S0 = {0.f,0.f}, S1 = {0.f,0.f}, S2 = {0.f,0.f},
               S3 = {0.f,0.f}, S4 = {0.f,0.f};

        {   // preload first row (hg0-R) into pp buffer 0
            const int h = hg0 - R_;
            float2 a = {0.f,0.f}, b = {0.f,0.f};
            if (h >= 0) { a = I2p[h * W2 + lane]; b = J2p[h * W2 + lane]; }
            bI[g][0][lane + 2] = a;
            bJ[g][0][lane + 2] = b;
        }
        __syncthreads();

        int cur = 0;
        for (int h = hg0 - R_; h < hg0 + HSUB + R_; h++) {
            // prefetch next row
            float2 nI = {0.f,0.f}, nJ = {0.f,0.f};
            const int hn = h + 1;
            if (hn >= 0 && hn < H_) {
                nI = I2p[hn * W2 + lane];
                nJ = J2p[hn * W2 + lane];
            }

            // gather 10 input values per array (5 aligned float2 cells)
            float vI[10], vJ[10];
#pragma unroll
            for (int j = 0; j < 5; j++) {
                const float2 cI = bI[g][cur][lane + j];
                const float2 cJ = bJ[g][cur][lane + j];
                vI[2*j] = cI.x; vI[2*j+1] = cI.y;
                vJ[2*j] = cJ.x; vJ[2*j+1] = cJ.y;
            }

            // even output = taps 0..8; odd = even - ch(0) + ch(9)
            float e0=0.f,e1=0.f,e2=0.f,e3=0.f,e4=0.f;
#pragma unroll
            for (int i = 0; i < 9; i++) {
                const float a = vI[i], b = vJ[i];
                e0 += a; e1 += b; e2 += a*a; e3 += b*b; e4 += a*b;
            }
            const float o0 = e0 - vI[0] + vI[9];
            const float o1 = e1 - vJ[0] + vJ[9];
            const float o2 = e2 - vI[0]*vI[0] + vI[9]*vI[9];
            const float o3 = e3 - vJ[0]*vJ[0] + vJ[9]*vJ[9];
            const float o4 = e4 - vI[0]*vJ[0] + vI[9]*vJ[9];

            // accumulate unrounded; store rounded for trailing subtract
            const int slot = (h + 36) % 9;
            ring[g][slot][0][lane] = __floats2half2_rn(e0, o0); S0.x += e0; S0.y += o0;
            ring[g][slot][1][lane] = __floats2half2_rn(e1, o1); S1.x += e1; S1.y += o1;
            ring[g][slot][2][lane] = __floats2half2_rn(e2, o2); S2.x += e2; S2.y += o2;
            ring[g][slot][3][lane] = __floats2half2_rn(e3, o3); S3.x += e3; S3.y += o3;
            ring[g][slot][4][lane] = __floats2half2_rn(e4, o4); S4.x += e4; S4.y += o4;

            const int ho = h - R_;
            if (ho >= hg0 && ho < hg0 + HSUB) {
                const size_t ob = (((size_t)d * HW_ + (size_t)ho * W_) >> 1) + lane;
                g_P01[ob] = make_float2(pack_h2(__floats2half2_rn(S0.x, S0.y)),
                                        pack_h2(__floats2half2_rn(S1.x, S1.y)));
                g_P23[ob] = make_float2(pack_h2(__floats2half2_rn(S2.x, S2.y)),
                                        pack_h2(__floats2half2_rn(S3.x, S3.y)));
                g_P4[ob]  = __floats2half2_rn(S4.x, S4.y);
            }
            const int hl = h - 2 * R_;
            if (hl >= hg0 - R_) {
                const int ls = (hl + 36) % 9;
                float2 f;
                f = __half22float2(ring[g][ls][0][lane]); S0.x -= f.x; S0.y -= f.y;
                f = __half22float2(ring[g][ls][1][lane]); S1.x -= f.x; S1.y -= f.y;
                f = __half22float2(ring[g][ls][2][lane]); S2.x -= f.x; S2.y -= f.y;
                f = __half22float2(ring[g][ls][3][lane]); S3.x -= f.x; S3.y -= f.y;
                f = __half22float2(ring[g][ls][4][lane]); S4.x -= f.x; S4.y -= f.y;
            }

            bI[g][cur ^ 1][lane + 2] = nI;
            bJ[g][cur ^ 1][lane + 2] = nJ;
            __syncthreads();
            cur ^= 1;
        }
    } else {
        // ----- gradient-loss partials; per-thread indices loop-invariant -----
        const int gid = bid - NBLK_WH;
        const int W4 = W_ / 4;                  // 40
        const int STRIDE = GBLK * TPB1;         // 122,880
        const float4* __restrict__ p4 = (const float4*)dsp;
        const float*  __restrict__ pf = dsp;
        const int w = tid;

        const int base = gid * TPB1 + w;        // < STRIDE
        const int wv  = base % W4;
        const int hh  = (base / W4) % H_;
        const int dd0 = base / (W4 * H_);       // 0..15
        const bool doW = (wv < W4 - 1);
        const bool doH = (hh < H_ - 1);

        float aH = 0.f, aD = 0.f, aW = 0.f;
        int i = base;
#pragma unroll
        for (int c = 0; c < 3; c++) {
#pragma unroll
            for (int j = 0; j < 10; j++) {
                const float4 v = p4[i];
                float t;
                t = v.y - v.x; aW += t * t;
                t = v.z - v.y; aW += t * t;
                t = v.w - v.z; aW += t * t;
                if (doW) { t = pf[i * 4 + 4] - v.w; aW += t * t; }
                if (doH) {
                    const float4 u = p4[i + W4];
                    t = u.x - v.x; aH += t * t;
                    t = u.y - v.y; aH += t * t;
                    t = u.z - v.z; aH += t * t;
                    t = u.w - v.w; aH += t * t;
                }
                if (dd0 + 16 * j < D_ - 1) {
                    const float4 u = p4[i + HW_ / 4];
                    t = u.x - v.x; aD += t * t;
                    t = u.y - v.y; aD += t * t;
                    t = u.z - v.z; aD += t * t;
                    t = u.w - v.w; aD += t * t;
                }
                i += STRIDE;
            }
        }

        __shared__ float sh[3][TPB1];
        sh[0][w] = aH; sh[1][w] = aD; sh[2][w] = aW;
        __syncthreads();
        if (w < 80) { sh[0][w] += sh[0][w+80]; sh[1][w] += sh[1][w+80]; sh[2][w] += sh[2][w+80]; }
        __syncthreads();
        if (w < 40) { sh[0][w] += sh[0][w+40]; sh[1][w] += sh[1][w+40]; sh[2][w] += sh[2][w+40]; }
        __syncthreads();
        if (w < 20) { sh[0][w] += sh[0][w+20]; sh[1][w] += sh[1][w+20]; sh[2][w] += sh[2][w+20]; }
        __syncthreads();
        if (w < 10) { sh[0][w] += sh[0][w+10]; sh[1][w] += sh[1][w+10]; sh[2][w] += sh[2][w+10]; }
        __syncthreads();
        if (w < 5)  { sh[0][w] += sh[0][w+5];  sh[1][w] += sh[1][w+5];  sh[2][w] += sh[2][w+5];  }
        __syncthreads();
        if (w == 0) {
            g_gpart[gid * 3 + 0] = sh[0][0] + sh[0][1] + sh[0][2] + sh[0][3] + sh[0][4];
            g_gpart[gid * 3 + 1] = sh[1][0] + sh[1][1] + sh[1][2] + sh[1][3] + sh[1][4];
            g_gpart[gid * 3 + 2] = sh[2][0] + sh[2][1] + sh[2][2] + sh[2][3] + sh[2][4];
        }
    }
}

// ---------------------------------------------------------------------------
// Kernel 2: D-axis running box sum over paired channels (2 voxels/thread)
// fused with simplified cc formula + block reduction; last block combines.
// grid = (30, 16), block = 512. d-loop fully unrolled so the compiler can
// hoist independent load addresses and batch-issue LDGs (fp order unchanged).
// ---------------------------------------------------------------------------
__global__ void __launch_bounds__(512, 2) k_B(float* __restrict__ out)
{
    const int t = threadIdx.x;
    const int p  = blockIdx.x * 512 + t;     // half2 position in a slice
    const int d0 = blockIdx.y * DCHUNK;

    float2 S0 = {0.f, 0.f}, S1 = {0.f, 0.f}, S2 = {0.f, 0.f},
           S3 = {0.f, 0.f}, S4 = {0.f, 0.f};

#pragma unroll
    for (int dd = d0 - R_; dd < d0 + R_; dd++) {
        if (dd >= 0 && dd < D_) {
            const int o = dd * HW2 + p;
            const float2 a = g_P01[o];
            const float2 b = g_P23[o];
            const __half2 c = g_P4[o];
            float2 v;
            v = __half22float2(unpack_h2(a.x)); S0.x += v.x; S0.y += v.y;
            v = __half22float2(unpack_h2(a.y)); S1.x += v.x; S1.y += v.y;
            v = __half22float2(unpack_h2(b.x)); S2.x += v.x; S2.y += v.y;
            v = __half22float2(unpack_h2(b.y)); S3.x += v.x; S3.y += v.y;
            v = __half22float2(c);              S4.x += v.x; S4.y += v.y;
        }
    }

    float acc = 0.f;
#pragma unroll
    for (int k = 0; k < DCHUNK; k++) {
        const int d = d0 + k;
        const int dn = d + R_;
        if (dn < D_) {
            const int o = dn * HW2 + p;
            const float2 a = g_P01[o];
            const float2 b = g_P23[o];
            const __half2 c = g_P4[o];
            float2 v;
            v = __half22float2(unpack_h2(a.x)); S0.x += v.x; S0.y += v.y;
            v = __half22float2(unpack_h2(a.y)); S1.x += v.x; S1.y += v.y;
            v = __half22float2(unpack_h2(b.x)); S2.x += v.x; S2.y += v.y;
            v = __half22float2(unpack_h2(b.y)); S3.x += v.x; S3.y += v.y;
            v = __half22float2(c);              S4.x += v.x; S4.y += v.y;
        }
        acc += ccf(S0.x, S1.x, S2.x, S3.x, S4.x);
        acc += ccf(S0.y, S1.y, S2.y, S3.y, S4.y);

        const int dp = d - R_;
        if (dp >= 0) {
            const int o = dp * HW2 + p;
            const float2 a = g_P01[o];
            const float2 b = g_P23[o];
            const __half2 c = g_P4[o];
            float2 v;
            v = __half22float2(unpack_h2(a.x)); S0.x -= v.x; S0.y -= v.y;
            v = __half22float2(unpack_h2(a.y)); S1.x -= v.x; S1.y -= v.y;
            v = __half22float2(unpack_h2(b.x)); S2.x -= v.x; S2.y -= v.y;
            v = __half22float2(unpack_h2(b.y)); S3.x -= v.x; S3.y -= v.y;
            v = __half22float2(c);              S4.x -= v.x; S4.y -= v.y;
        }
    }

    __shared__ float sh[512];
    sh[t] = acc;
    __syncthreads();
#pragma unroll
    for (int s = 256; s > 0; s >>= 1) {
        if (t < s) sh[t] += sh[t + s];
        __syncthreads();
    }
    if (t == 0) g_ccpart[blockIdx.y * GRID3X + blockIdx.x] = sh[0];

    // ----- last-block final combine -----
    __shared__ bool is_last;
    if (t == 0) {
        __threadfence();
        is_last = (atomicAdd(&g_cnt, 1u) == NPART3 - 1);
    }
    __syncthreads();
    if (!is_last) return;

    float cc = 0.f;
    for (int i = t; i < NPART3; i += 512) cc += g_ccpart[i];

    const float invNH = 1.0f / (3.0f * D_ * (H_ - 1) * W_);
    const float invND = 1.0f / (3.0f * (D_ - 1) * H_ * W_);
    const float invNW = 1.0f / (3.0f * D_ * H_ * (W_ - 1));

    float g = 0.f;
    for (int i = t; i < GBLK; i += 512) {
        g += g_gpart[i * 3 + 0] * invNH
           + g_gpart[i * 3 + 1] * invND
           + g_gpart[i * 3 + 2] * invNW;
    }

    __shared__ float shg[512];
    sh[t] = cc;
    shg[t] = g;
    __syncthreads();
#pragma unroll
    for (int s = 256; s > 0; s >>= 1) {
        if (t < s) { sh[t] += sh[t + s]; shg[t] += shg[t + s]; }
        __syncthreads();
    }
    if (t == 0)
        out[0] = (1.0f - sh[0] / (float)N_) + 0.01f * (shg[0] / 3.0f);
}

extern "C" void kernel_launch(void* const* d_in, const int* in_sizes, int n_in,
                              void* d_out, int out_size)
{
    const float* I   = (const float*)d_in[0];
    const float* J   = (const float*)d_in[1];
    const float* dsp = (const float*)d_in[2];
    float* out = (float*)d_out;

    k_A<<<NBLK_WH + GBLK, TPB1>>>(I, J, dsp);
    k_B<<<dim3(GRID3X, GRID3Y), 512>>>(out);
}

// round 16
// speedup vs baseline: 1.1845x; 1.0630x over previous
#include <cuda_runtime.h>
#include <cuda_fp16.h>

#define D_ 160
#define H_ 192
#define W_ 160
#define HW_ (H_ * W_)
#define N_ (D_ * H_ * W_)          // 4,915,200
#define NP_ (N_ / 2)                // voxel pairs
#define R_ 4
#define INV_WSZ (1.0f / 729.0f)

#define W2 (W_ / 2)                 // 80 float2 lanes per row
#define HSUB 32                     // output rows per 80-lane group
#define NHCH (H_ / (2 * HSUB))      // 3 (each block = 2 groups = 64 rows)
#define NBLK_WH (D_ * NHCH)         // 480
#define GBLK 768
#define TPB1 160

#define DCHUNK 8
#define HW2 (HW_ / 2)               // 15360 half2 positions per slice
#define GRID3X (HW2 / 512)          // 30
#define GRID3Y (D_ / DCHUNK)        // 20
#define NPART3 (GRID3X * GRID3Y)    // 600

// Scratch — W+H box sums in fp16: ch0..3 packed in one float4 (4x half2),
// ch4 separate half2.
__device__ float4  g_P03[NP_];
__device__ __half2 g_P4[NP_];
__device__ float g_ccpart[NPART3];
__device__ float g_gpart[GBLK * 3];
__device__ unsigned int g_cnt;

__device__ __forceinline__ float pack_h2(__half2 h)
{
    return __uint_as_float(*reinterpret_cast<unsigned int*>(&h));
}
__device__ __forceinline__ __half2 unpack_h2(float f)
{
    unsigned int u = __float_as_uint(f);
    return *reinterpret_cast<__half2*>(&u);
}

// Simplified LNCC term: cross = S4 - S0*S1/729, Iv = S2 - S0^2/729, Jv = S3 - S1^2/729
__device__ __forceinline__ float ccf(float s0, float s1, float s2, float s3, float s4)
{
    const float cross = fmaf(-s0 * s1, INV_WSZ, s4);
    const float Iv    = fmaf(-s0 * s0, INV_WSZ, s2);
    const float Jv    = fmaf(-s1 * s1, INV_WSZ, s3);
    return __fdividef(cross * cross, fmaf(Iv, Jv, 1e-5f));
}

// ---------------------------------------------------------------------------
// Kernel 1, blocks [0, NBLK_WH): fused W+H box-sum, 2 voxels/thread.
// 160 threads = 2 groups x 80 lanes; 9-slot fp16 smem ring; ping-pong float2
// row buffers (1 sync/row). Blocks [NBLK_WH, +GBLK): gradient-loss partials.
// (R13-proven structure; only the output packing changed.)
// ---------------------------------------------------------------------------
__global__ void __launch_bounds__(TPB1) k_A(const float* __restrict__ I,
                                            const float* __restrict__ J,
                                            const float* __restrict__ dsp)
{
    const int bid = blockIdx.x;
    const int tid = threadIdx.x;

    if (bid == 0 && tid == 0) g_cnt = 0u;   // reset for graph replay

    if (bid < NBLK_WH) {
        __shared__ float2  bI[2][2][W2 + 4];   // [group][pp][cell]
        __shared__ float2  bJ[2][2][W2 + 4];
        __shared__ __half2 ring[2][9][5][W2];

        const int g    = tid / W2;             // 0 or 1
        const int lane = tid % W2;             // 0..79
        const int d    = bid / NHCH;
        const int hg0  = (bid % NHCH) * (2 * HSUB) + g * HSUB;

        if (lane < 2) {
#pragma unroll
            for (int pp = 0; pp < 2; pp++) {
                bI[g][pp][lane] = make_float2(0.f, 0.f);
                bI[g][pp][W2 + 2 + lane] = make_float2(0.f, 0.f);
                bJ[g][pp][lane] = make_float2(0.f, 0.f);
                bJ[g][pp][W2 + 2 + lane] = make_float2(0.f, 0.f);
            }
        }

        const float2* __restrict__ I2p = (const float2*)(I + (size_t)d * HW_);
        const float2* __restrict__ J2p = (const float2*)(J + (size_t)d * HW_);

        float2 S0 = {0.f,0.f}, S1 = {0.f,0.f}, S2 = {0.f,0.f},
               S3 = {0.f,0.f}, S4 = {0.f,0.f};

        {   // preload first row (hg0-R) into pp buffer 0
            const int h = hg0 - R_;
            float2 a = {0.f,0.f}, b = {0.f,0.f};
            if (h >= 0) { a = I2p[h * W2 + lane]; b = J2p[h * W2 + lane]; }
            bI[g][0][lane + 2] = a;
            bJ[g][0][lane + 2] = b;
        }
        __syncthreads();

        int cur = 0;
        for (int h = hg0 - R_; h < hg0 + HSUB + R_; h++) {
            // prefetch next row
            float2 nI = {0.f,0.f}, nJ = {0.f,0.f};
            const int hn = h + 1;
            if (hn >= 0 && hn < H_) {
                nI = I2p[hn * W2 + lane];
                nJ = J2p[hn * W2 + lane];
            }

            // gather 10 input values per array (5 aligned float2 cells)
            float vI[10], vJ[10];
#pragma unroll
            for (int j = 0; j < 5; j++) {
                const float2 cI = bI[g][cur][lane + j];
                const float2 cJ = bJ[g][cur][lane + j];
                vI[2*j] = cI.x; vI[2*j+1] = cI.y;
                vJ[2*j] = cJ.x; vJ[2*j+1] = cJ.y;
            }

            // even output = taps 0..8; odd = even - ch(0) + ch(9)
            float e0=0.f,e1=0.f,e2=0.f,e3=0.f,e4=0.f;
#pragma unroll
            for (int i = 0; i < 9; i++) {
                const float a = vI[i], b = vJ[i];
                e0 += a; e1 += b; e2 += a*a; e3 += b*b; e4 += a*b;
            }
            const float o0 = e0 - vI[0] + vI[9];
            const float o1 = e1 - vJ[0] + vJ[9];
            const float o2 = e2 - vI[0]*vI[0] + vI[9]*vI[9];
            const float o3 = e3 - vJ[0]*vJ[0] + vJ[9]*vJ[9];
            const float o4 = e4 - vI[0]*vJ[0] + vI[9]*vJ[9];

            // accumulate unrounded; store rounded for trailing subtract
            const int slot = (h + 36) % 9;
            ring[g][slot][0][lane] = __floats2half2_rn(e0, o0); S0.x += e0; S0.y += o0;
            ring[g][slot][1][lane] = __floats2half2_rn(e1, o1); S1.x += e1; S1.y += o1;
            ring[g][slot][2][lane] = __floats2half2_rn(e2, o2); S2.x += e2; S2.y += o2;
            ring[g][slot][3][lane] = __floats2half2_rn(e3, o3); S3.x += e3; S3.y += o3;
            ring[g][slot][4][lane] = __floats2half2_rn(e4, o4); S4.x += e4; S4.y += o4;

            const int ho = h - R_;
            if (ho >= hg0 && ho < hg0 + HSUB) {
                const size_t ob = (((size_t)d * HW_ + (size_t)ho * W_) >> 1) + lane;
                g_P03[ob] = make_float4(pack_h2(__floats2half2_rn(S0.x, S0.y)),
                                        pack_h2(__floats2half2_rn(S1.x, S1.y)),
                                        pack_h2(__floats2half2_rn(S2.x, S2.y)),
                                        pack_h2(__floats2half2_rn(S3.x, S3.y)));
                g_P4[ob]  = __floats2half2_rn(S4.x, S4.y);
            }
            const int hl = h - 2 * R_;
            if (hl >= hg0 - R_) {
                const int ls = (hl + 36) % 9;
                float2 f;
                f = __half22float2(ring[g][ls][0][lane]); S0.x -= f.x; S0.y -= f.y;
                f = __half22float2(ring[g][ls][1][lane]); S1.x -= f.x; S1.y -= f.y;
                f = __half22float2(ring[g][ls][2][lane]); S2.x -= f.x; S2.y -= f.y;
                f = __half22float2(ring[g][ls][3][lane]); S3.x -= f.x; S3.y -= f.y;
                f = __half22float2(ring[g][ls][4][lane]); S4.x -= f.x; S4.y -= f.y;
            }

            bI[g][cur ^ 1][lane + 2] = nI;
            bJ[g][cur ^ 1][lane + 2] = nJ;
            __syncthreads();
            cur ^= 1;
        }
    } else {
        // ----- gradient-loss partials; per-thread indices loop-invariant -----
        const int gid = bid - NBLK_WH;
        const int W4 = W_ / 4;                  // 40
        const int STRIDE = GBLK * TPB1;         // 122,880
        const float4* __restrict__ p4 = (const float4*)dsp;
        const float*  __restrict__ pf = dsp;
        const int w = tid;

        const int base = gid * TPB1 + w;        // < STRIDE
        const int wv  = base % W4;
        const int hh  = (base / W4) % H_;
        const int dd0 = base / (W4 * H_);       // 0..15
        const bool doW = (wv < W4 - 1);
        const bool doH = (hh < H_ - 1);

        float aH = 0.f, aD = 0.f, aW = 0.f;
        int i = base;
#pragma unroll
        for (int c = 0; c < 3; c++) {
#pragma unroll
            for (int j = 0; j < 10; j++) {
                const float4 v = p4[i];
                float t;
                t = v.y - v.x; aW += t * t;
                t = v.z - v.y; aW += t * t;
                t = v.w - v.z; aW += t * t;
                if (doW) { t = pf[i * 4 + 4] - v.w; aW += t * t; }
                if (doH) {
                    const float4 u = p4[i + W4];
                    t = u.x - v.x; aH += t * t;
                    t = u.y - v.y; aH += t * t;
                    t = u.z - v.z; aH += t * t;
                    t = u.w - v.w; aH += t * t;
                }
                if (dd0 + 16 * j < D_ - 1) {
                    const float4 u = p4[i + HW_ / 4];
                    t = u.x - v.x; aD += t * t;
                    t = u.y - v.y; aD += t * t;
                    t = u.z - v.z; aD += t * t;
                    t = u.w - v.w; aD += t * t;
                }
                i += STRIDE;
            }
        }

        __shared__ float sh[3][TPB1];
        sh[0][w] = aH; sh[1][w] = aD; sh[2][w] = aW;
        __syncthreads();
        if (w < 80) { sh[0][w] += sh[0][w+80]; sh[1][w] += sh[1][w+80]; sh[2][w] += sh[2][w+80]; }
        __syncthreads();
        if (w < 40) { sh[0][w] += sh[0][w+40]; sh[1][w] += sh[1][w+40]; sh[2][w] += sh[2][w+40]; }
        __syncthreads();
        if (w < 20) { sh[0][w] += sh[0][w+20]; sh[1][w] += sh[1][w+20]; sh[2][w] += sh[2][w+20]; }
        __syncthreads();
        if (w < 10) { sh[0][w] += sh[0][w+10]; sh[1][w] += sh[1][w+10]; sh[2][w] += sh[2][w+10]; }
        __syncthreads();
        if (w < 5)  { sh[0][w] += sh[0][w+5];  sh[1][w] += sh[1][w+5];  sh[2][w] += sh[2][w+5];  }
        __syncthreads();
        if (w == 0) {
            g_gpart[gid * 3 + 0] = sh[0][0] + sh[0][1] + sh[0][2] + sh[0][3] + sh[0][4];
            g_gpart[gid * 3 + 1] = sh[1][0] + sh[1][1] + sh[1][2] + sh[1][3] + sh[1][4];
            g_gpart[gid * 3 + 2] = sh[2][0] + sh[2][1] + sh[2][2] + sh[2][3] + sh[2][4];
        }
    }
}

// ---------------------------------------------------------------------------
// Kernel 2: D-axis running box sum (2 voxels/thread, 2 loads per slice:
// LDG.128 + LDG.32) fused with simplified cc formula + block reduction;
// last block combines. grid = (30, 20), block = 512.
// ---------------------------------------------------------------------------
__global__ void __launch_bounds__(512) k_B(float* __restrict__ out)
{
    const int t = threadIdx.x;
    const int p  = blockIdx.x * 512 + t;     // half2 position in a slice
    const int d0 = blockIdx.y * DCHUNK;

    float2 S0 = {0.f, 0.f}, S1 = {0.f, 0.f}, S2 = {0.f, 0.f},
           S3 = {0.f, 0.f}, S4 = {0.f, 0.f};

#pragma unroll
    for (int dd = d0 - R_; dd < d0 + R_; dd++) {
        if (dd >= 0 && dd < D_) {
            const int o = dd * HW2 + p;
            const float4 a = g_P03[o];
            const __half2 c = g_P4[o];
            float2 v;
            v = __half22float2(unpack_h2(a.x)); S0.x += v.x; S0.y += v.y;
            v = __half22float2(unpack_h2(a.y)); S1.x += v.x; S1.y += v.y;
            v = __half22float2(unpack_h2(a.z)); S2.x += v.x; S2.y += v.y;
            v = __half22float2(unpack_h2(a.w)); S3.x += v.x; S3.y += v.y;
            v = __half22float2(c);              S4.x += v.x; S4.y += v.y;
        }
    }

    float acc = 0.f;
    for (int d = d0; d < d0 + DCHUNK; d++) {
        const int dn = d + R_;
        if (dn < D_) {
            const int o = dn * HW2 + p;
            const float4 a = g_P03[o];
            const __half2 c = g_P4[o];
            float2 v;
            v = __half22float2(unpack_h2(a.x)); S0.x += v.x; S0.y += v.y;
            v = __half22float2(unpack_h2(a.y)); S1.x += v.x; S1.y += v.y;
            v = __half22float2(unpack_h2(a.z)); S2.x += v.x; S2.y += v.y;
            v = __half22float2(unpack_h2(a.w)); S3.x += v.x; S3.y += v.y;
            v = __half22float2(c);              S4.x += v.x; S4.y += v.y;
        }
        acc += ccf(S0.x, S1.x, S2.x, S3.x, S4.x);
        acc += ccf(S0.y, S1.y, S2.y, S3.y, S4.y);

        const int dp = d - R_;
        if (dp >= 0) {
            const int o = dp * HW2 + p;
            const float4 a = g_P03[o];
            const __half2 c = g_P4[o];
            float2 v;
            v = __half22float2(unpack_h2(a.x)); S0.x -= v.x; S0.y -= v.y;
            v = __half22float2(unpack_h2(a.y)); S1.x -= v.x; S1.y -= v.y;
            v = __half22float2(unpack_h2(a.z)); S2.x -= v.x; S2.y -= v.y;
            v = __half22float2(unpack_h2(a.w)); S3.x -= v.x; S3.y -= v.y;
            v = __half22float2(c);              S4.x -= v.x; S4.y -= v.y;
        }
    }

    __shared__ float sh[512];
    sh[t] = acc;
    __syncthreads();
#pragma unroll
    for (int s = 256; s > 0; s >>= 1) {
        if (t < s) sh[t] += sh[t + s];
        __syncthreads();
    }
    if (t == 0) g_ccpart[blockIdx.y * GRID3X + blockIdx.x] = sh[0];

    // ----- last-block final combine -----
    __shared__ bool is_last;
    if (t == 0) {
        __threadfence();
        is_last = (atomicAdd(&g_cnt, 1u) == NPART3 - 1);
    }
    __syncthreads();
    if (!is_last) return;

    float cc = 0.f;
    for (int i = t; i < NPART3; i += 512) cc += g_ccpart[i];

    const float invNH = 1.0f / (3.0f * D_ * (H_ - 1) * W_);
    const float invND = 1.0f / (3.0f * (D_ - 1) * H_ * W_);
    const float invNW = 1.0f / (3.0f * D_ * H_ * (W_ - 1));

    float g = 0.f;
    for (int i = t; i < GBLK; i += 512) {
        g += g_gpart[i * 3 + 0] * invNH
           + g_gpart[i * 3 + 1] * invND
           + g_gpart[i * 3 + 2] * invNW;
    }

    __shared__ float shg[512];
    sh[t] = cc;
    shg[t] = g;
    __syncthreads();
#pragma unroll
    for (int s = 256; s > 0; s >>= 1) {
        if (t < s) { sh[t] += sh[t + s]; shg[t] += shg[t + s]; }
        __syncthreads();
    }
    if (t == 0)
        out[0] = (1.0f - sh[0] / (float)N_) + 0.01f * (shg[0] / 3.0f);
}

extern "C" void kernel_launch(void* const* d_in, const int* in_sizes, int n_in,
                              void* d_out, int out_size)
{
    const float* I   = (const float*)d_in[0];
    const float* J   = (const float*)d_in[1];
    const float* dsp = (const float*)d_in[2];
    float* out = (float*)d_out;

    k_A<<<NBLK_WH + GBLK, TPB1>>>(I, J, dsp);
    k_B<<<dim3(GRID3X, GRID3Y), 512>>>(out);
}